// round 2
// baseline (speedup 1.0000x reference)
#include <cuda_runtime.h>
#include <math.h>

#define N 512
#define C 157
#define M 20
#define NC (N*C)
#define SIGMA2_INV (1.0f/(2.0f*300.0f*300.0f))
#define EPSV 1e-7f
#define INV_DECAY (1.0f/0.9f)

__device__ float g_partial[N];

__global__ __launch_bounds__(256) void fused_kernel(
    const float* __restrict__ a, const float* __restrict__ aa,
    const float* __restrict__ target, const float* __restrict__ bank_values,
    const int* __restrict__ bank_times, const int* __restrict__ bank_mask,
    const int* __restrict__ ids, const int* __restrict__ times,
    float* __restrict__ out)
{
    extern __shared__ float aa_s[];  // C*C floats = 98596 B
    __shared__ float msg_s[C], fmsg_s[C];
    __shared__ float wpast[M], wfut[M];
    __shared__ float denp_s, denf_s;
    __shared__ int id_s;
    __shared__ float sred[256];

    const int n = blockIdx.x;
    const int t = threadIdx.x;

    // Phase 0: thread 0 computes the 20 temporal weights (exact replication of
    // the exclusive-rank decay product: dw = (1/decay)^rank, rank over valid entries)
    if (t == 0) {
        int id = ids[n];
        id_s = id;
        float t0 = (float)times[n];
        float denp = 0.f, denf = 0.f, curp = 1.f, curf = 1.f;
        #pragma unroll
        for (int m = 0; m < M; m++) {
            int tsi = bank_times[id*M + m];
            bool mk = bank_mask[id*M + m] != 0;   // int32 mask (bool normalized by harness)
            float ts = (float)tsi;
            float d = ts - t0;
            float kern = expf(-d*d*SIGMA2_INV);
            if (mk && ts < t0) { wpast[m] = curp*kern; denp += curp; curp *= INV_DECAY; }
            else wpast[m] = 0.f;
            if (mk && ts > t0) { wfut[m] = curf*kern; denf += curf; curf *= INV_DECAY; }
            else wfut[m] = 0.f;
        }
        denp_s = denp; denf_s = denf;
    }
    __syncthreads();

    // Phase 1: stream aa[n] (98.6 KB) into smem, coalesced.
    const float* aa_g = aa + (size_t)n * (C*C);
    #pragma unroll 4
    for (int e = t; e < C*C; e += 256) aa_s[e] = aa_g[e];

    // Phase 2: msg/fmsg — one pass over bank_values serves both
    if (t < C) {
        const float* vals = bank_values + (size_t)id_s * (M*C);
        float nump = 0.f, numf = 0.f;
        #pragma unroll
        for (int m = 0; m < M; m++) {
            float v = vals[m*C + t];
            nump += wpast[m]*v;
            numf += wfut[m]*v;
        }
        float denp = denp_s, denf = denf_s;
        msg_s[t]  = (denp > 0.f) ? nump / fmaxf(denp, EPSV) : 0.f;
        fmsg_s[t] = (denf > 0.f) ? numf / fmaxf(denf, EPSV) : 0.f;
    }
    __syncthreads();

    // Phase 3: qa[t] = sigmoid(a + sum_i aa[i][t]*msg[i] + sum_i aa[t][i]*fmsg[i])
    // plus fused BCE partials. Stride-157 smem rows are bank-conflict-free (gcd(29,32)=1).
    float s = 0.f;
    if (t < C) {
        float col = 0.f, row = 0.f;
        #pragma unroll 4
        for (int i = 0; i < C; i++) {
            col += aa_s[i*C + t] * msg_s[i];
            row += aa_s[t*C + i] * fmsg_s[i];
        }
        float av = a[n*C + t];
        float x = av + col + row;
        float qa = 1.f / (1.f + expf(-x));
        out[n*C + t] = qa;
        float tg = target[n*C + t];
        float p1 = fminf(fmaxf(qa, EPSV), 1.f - EPSV);
        s  = tg*logf(p1) + (1.f - tg)*logf(1.f - p1);
        float p2 = 1.f / (1.f + expf(-av));
        p2 = fminf(fmaxf(p2, EPSV), 1.f - EPSV);
        s += tg*logf(p2) + (1.f - tg)*logf(1.f - p2);
    }
    // deterministic block tree-reduce
    sred[t] = s;
    __syncthreads();
    #pragma unroll
    for (int off = 128; off > 0; off >>= 1) {
        if (t < off) sred[t] += sred[t + off];
        __syncthreads();
    }
    if (t == 0) g_partial[n] = sred[0];
}

__global__ void loss_kernel(float* __restrict__ out, int out_size) {
    __shared__ float sred[512];
    int t = threadIdx.x;
    sred[t] = g_partial[t];
    __syncthreads();
    #pragma unroll
    for (int off = 256; off > 0; off >>= 1) {
        if (t < off) sred[t] += sred[t + off];
        __syncthreads();
    }
    if (t == 0 && out_size > NC) out[NC] = -sred[0] / (3.0f * (float)NC);
}

extern "C" void kernel_launch(void* const* d_in, const int* in_sizes, int n_in,
                              void* d_out, int out_size) {
    const float* a           = (const float*)d_in[0];
    const float* aa          = (const float*)d_in[1];
    const float* target      = (const float*)d_in[2];
    const float* bank_values = (const float*)d_in[3];
    const int*   bank_times  = (const int*)d_in[4];
    const int*   bank_mask   = (const int*)d_in[5];
    const int*   ids         = (const int*)d_in[6];
    const int*   times       = (const int*)d_in[7];
    float* out = (float*)d_out;

    int smem = C * C * sizeof(float);
    cudaFuncSetAttribute(fused_kernel, cudaFuncAttributeMaxDynamicSharedMemorySize, smem);
    fused_kernel<<<N, 256, smem>>>(a, aa, target, bank_values, bank_times,
                                   bank_mask, ids, times, out);
    loss_kernel<<<1, 512>>>(out, out_size);
}

// round 3
// speedup vs baseline: 1.1764x; 1.1764x over previous
#include <cuda_runtime.h>
#include <math.h>

#define N 512
#define C 157
#define M 20
#define NC (N*C)
#define SIGMA2_INV (1.0f/(2.0f*300.0f*300.0f))
#define EPSV 1e-7f
#define INV_DECAY (1.0f/0.9f)
#define LOG2_INV_DECAY 0.15200309344504997f   /* log2(1/0.9) */

#define CH 40                       /* rows per chunk */
#define NCHUNK 4                    /* 40+40+40+37 = 157 */
#define CHELEMS (CH*C)              /* 6280 floats per chunk buffer */

__device__ float g_partial[N];
__device__ unsigned int g_count = 0;

__device__ __forceinline__ void cp_async4(void* s, const void* g) {
    unsigned saddr = (unsigned)__cvta_generic_to_shared(s);
    asm volatile("cp.async.ca.shared.global [%0], [%1], 4;\n" :: "r"(saddr), "l"(g));
}
__device__ __forceinline__ void cp_commit() {
    asm volatile("cp.async.commit_group;\n" ::: "memory");
}
template<int Nw> __device__ __forceinline__ void cp_wait() {
    asm volatile("cp.async.wait_group %0;\n" :: "n"(Nw) : "memory");
}

__global__ __launch_bounds__(256) void fused_kernel(
    const float* __restrict__ a, const float* __restrict__ aa,
    const float* __restrict__ target, const float* __restrict__ bank_values,
    const int* __restrict__ bank_times, const int* __restrict__ bank_mask,
    const int* __restrict__ ids, const int* __restrict__ times,
    float* __restrict__ out, int out_size)
{
    extern __shared__ float buf[];          // 2 * CHELEMS floats = 50240 B
    __shared__ float msg_s[C], fmsg_s[C];
    __shared__ float wpast[M], wfut[M];
    __shared__ float denp_s, denf_s;
    __shared__ float sred[256];
    __shared__ int last_s;

    const int n = blockIdx.x;
    const int t = threadIdx.x;
    const int id = ids[n];                  // uniform broadcast load
    const float* aa_g = aa + (size_t)n * (C*C);

    // ---- prefetch chunk 0 of aa (async, no register dependency) ----
    {
        const float* src = aa_g;
        float* dst = buf;
        #pragma unroll 4
        for (int e = t; e < CH*C; e += 256) cp_async4(dst + e, src + e);
        cp_commit();
    }

    // ---- parallel temporal-weight computation (warp 0, ballot rank) ----
    if (t < 32) {
        const int lane = t;
        const bool v = lane < M;
        int tsi = 0, mk = 0;
        if (v) { tsi = bank_times[id*M + lane]; mk = bank_mask[id*M + lane]; }
        const float t0 = (float)times[n];
        float ts = (float)tsi;
        float d = ts - t0;
        float kern = expf(-d*d*SIGMA2_INV);
        bool condp = v && mk && (ts < t0);
        bool condf = v && mk && (ts > t0);
        unsigned bp = __ballot_sync(0xFFFFFFFFu, condp);
        unsigned bf = __ballot_sync(0xFFFFFFFFu, condf);
        unsigned below = (1u << lane) - 1u;
        float dwp = condp ? exp2f(LOG2_INV_DECAY * (float)__popc(bp & below)) : 0.f;
        float dwf = condf ? exp2f(LOG2_INV_DECAY * (float)__popc(bf & below)) : 0.f;
        if (v) { wpast[lane] = dwp * kern; wfut[lane] = dwf * kern; }
        if (lane == 0) {
            // den = sum_{r=0}^{cnt-1} (1/d)^r = ((1/d)^cnt - 1)/((1/d) - 1)
            float cp_ = (float)__popc(bp), cf_ = (float)__popc(bf);
            denp_s = (exp2f(LOG2_INV_DECAY * cp_) - 1.f) / (INV_DECAY - 1.f);
            denf_s = (exp2f(LOG2_INV_DECAY * cf_) - 1.f) / (INV_DECAY - 1.f);
        }
    }
    __syncthreads();

    // ---- msg/fmsg: one pass over bank_values serves both (overlaps chunk-0 load) ----
    if (t < C) {
        const float* vals = bank_values + (size_t)id * (M*C);
        float nump = 0.f, numf = 0.f;
        #pragma unroll
        for (int m = 0; m < M; m++) {
            float v = vals[m*C + t];
            nump += wpast[m]*v;
            numf += wfut[m]*v;
        }
        float denp = denp_s, denf = denf_s;
        msg_s[t]  = (denp > 0.f) ? nump / fmaxf(denp, EPSV) : 0.f;
        fmsg_s[t] = (denf > 0.f) ? numf / fmaxf(denf, EPSV) : 0.f;
    }
    __syncthreads();

    // ---- pipelined einsums over aa chunks ----
    float col = 0.f, row = 0.f;
    #pragma unroll
    for (int k = 0; k < NCHUNK; k++) {
        if (k + 1 < NCHUNK) {   // prefetch next chunk into the other buffer
            int r0n = (k+1)*CH;
            int cntn = ((C - r0n) < CH ? (C - r0n) : CH) * C;
            const float* src = aa_g + r0n*C;
            float* dst = buf + ((k+1)&1)*CHELEMS;
            #pragma unroll 4
            for (int e = t; e < cntn; e += 256) cp_async4(dst + e, src + e);
            cp_commit();
            cp_wait<1>();
        } else {
            cp_wait<0>();
        }
        __syncthreads();

        const float* bc = buf + (k&1)*CHELEMS;
        const int r0 = k*CH;
        const int rows = (C - r0) < CH ? (C - r0) : CH;
        if (t < C) {
            #pragma unroll 4
            for (int i = 0; i < rows; i++)
                col += bc[i*C + t] * msg_s[r0 + i];
            if (t >= r0 && t < r0 + rows) {
                const float* rp = bc + (t - r0)*C;
                #pragma unroll 4
                for (int j = 0; j < C; j++)
                    row += rp[j] * fmsg_s[j];
            }
        }
        __syncthreads();    // protect buf[k&1] before it is refilled at k+2
    }

    // ---- epilogue: qa, fused double-BCE partials ----
    float s = 0.f;
    if (t < C) {
        float av = a[n*C + t];
        float tg = target[n*C + t];
        float x = av + col + row;
        float qa = 1.f / (1.f + expf(-x));
        out[n*C + t] = qa;
        float p1 = fminf(fmaxf(qa, EPSV), 1.f - EPSV);
        s  = tg*logf(p1) + (1.f - tg)*logf(1.f - p1);
        float p2 = 1.f / (1.f + expf(-av));
        p2 = fminf(fmaxf(p2, EPSV), 1.f - EPSV);
        s += tg*logf(p2) + (1.f - tg)*logf(1.f - p2);
    }
    sred[t] = s;
    __syncthreads();
    #pragma unroll
    for (int off = 128; off > 0; off >>= 1) {
        if (t < off) sred[t] += sred[t + off];
        __syncthreads();
    }
    if (t == 0) {
        g_partial[n] = sred[0];
        __threadfence();
        unsigned old = atomicAdd(&g_count, 1u);
        last_s = (old == N - 1);
    }
    __syncthreads();

    // ---- last CTA folds the 512 partials (deterministic fixed-order tree) ----
    if (last_s) {
        sred[t] = g_partial[t] + g_partial[t + 256];
        __syncthreads();
        #pragma unroll
        for (int off = 128; off > 0; off >>= 1) {
            if (t < off) sred[t] += sred[t + off];
            __syncthreads();
        }
        if (t == 0) {
            if (out_size > NC) out[NC] = -sred[0] / (3.0f * (float)NC);
            g_count = 0;        // reset for next graph replay
        }
    }
}

extern "C" void kernel_launch(void* const* d_in, const int* in_sizes, int n_in,
                              void* d_out, int out_size) {
    const float* a           = (const float*)d_in[0];
    const float* aa          = (const float*)d_in[1];
    const float* target      = (const float*)d_in[2];
    const float* bank_values = (const float*)d_in[3];
    const int*   bank_times  = (const int*)d_in[4];
    const int*   bank_mask   = (const int*)d_in[5];
    const int*   ids         = (const int*)d_in[6];
    const int*   times       = (const int*)d_in[7];
    float* out = (float*)d_out;

    int smem = 2 * CHELEMS * sizeof(float);   // 50240 B dynamic
    cudaFuncSetAttribute(fused_kernel, cudaFuncAttributeMaxDynamicSharedMemorySize, smem);
    fused_kernel<<<N, 256, smem>>>(a, aa, target, bank_values, bank_times,
                                   bank_mask, ids, times, out, out_size);
}

// round 4
// speedup vs baseline: 1.6383x; 1.3926x over previous
#include <cuda_runtime.h>
#include <math.h>

#define N 512
#define C 157
#define M 20
#define NC (N*C)
#define SIGMA2_INV (1.0f/(2.0f*300.0f*300.0f))
#define EPSV 1e-7f
#define INV_DECAY (1.0f/0.9f)
#define LOG2_INV_DECAY 0.15200309344504997f   /* log2(1/0.9) */

__device__ float g_partial[N];
__device__ unsigned int g_count = 0;

__global__ __launch_bounds__(256) void fused_kernel(
    const float* __restrict__ a, const float* __restrict__ aa,
    const float* __restrict__ target, const float* __restrict__ bank_values,
    const int* __restrict__ bank_times, const int* __restrict__ bank_mask,
    const int* __restrict__ ids, const int* __restrict__ times,
    float* __restrict__ out, int out_size)
{
    __shared__ float msg_s[C], fmsg_s[C];
    __shared__ float row_s[C];
    __shared__ float colpart[8][160];       // per-warp col partials (+pad)
    __shared__ float wpast[M], wfut[M];
    __shared__ float denp_s, denf_s;
    __shared__ float sred[256];
    __shared__ int last_s;

    const int n = blockIdx.x;
    const int t = threadIdx.x;
    const int w = t >> 5;
    const int l = t & 31;
    const int id = ids[n];
    const float* aa_g = aa + (size_t)n * (C*C);

    // ---- temporal weights: warp 0, ballot-rank (parallel, no serial chain) ----
    if (t < 32) {
        const bool v = l < M;
        int tsi = 0, mk = 0;
        if (v) { tsi = bank_times[id*M + l]; mk = bank_mask[id*M + l]; }
        const float t0 = (float)times[n];
        float ts = (float)tsi;
        float d = ts - t0;
        float kern = expf(-d*d*SIGMA2_INV);
        bool condp = v && mk && (ts < t0);
        bool condf = v && mk && (ts > t0);
        unsigned bp = __ballot_sync(0xFFFFFFFFu, condp);
        unsigned bf = __ballot_sync(0xFFFFFFFFu, condf);
        unsigned below = (1u << l) - 1u;
        float dwp = condp ? exp2f(LOG2_INV_DECAY * (float)__popc(bp & below)) : 0.f;
        float dwf = condf ? exp2f(LOG2_INV_DECAY * (float)__popc(bf & below)) : 0.f;
        if (v) { wpast[l] = dwp * kern; wfut[l] = dwf * kern; }
        if (l == 0) {
            // den = geometric series ((1/d)^cnt - 1)/((1/d) - 1)
            float cp_ = (float)__popc(bp), cf_ = (float)__popc(bf);
            denp_s = (exp2f(LOG2_INV_DECAY * cp_) - 1.f) / (INV_DECAY - 1.f);
            denf_s = (exp2f(LOG2_INV_DECAY * cf_) - 1.f) / (INV_DECAY - 1.f);
        }
    }
    __syncthreads();

    // ---- msg/fmsg: one pass over bank_values serves both ----
    if (t < C) {
        const float* vals = bank_values + (size_t)id * (M*C);
        float nump = 0.f, numf = 0.f;
        #pragma unroll
        for (int m = 0; m < M; m++) {
            float v = vals[m*C + t];
            nump += wpast[m]*v;
            numf += wfut[m]*v;
        }
        float denp = denp_s, denf = denf_s;
        msg_s[t]  = (denp > 0.f) ? nump / fmaxf(denp, EPSV) : 0.f;
        fmsg_s[t] = (denf > 0.f) ? numf / fmaxf(denf, EPSV) : 0.f;
    }
    __syncthreads();

    // ---- single streaming pass over aa: registers only, no staging ----
    // lane l owns cols j = l+32q (q=0..4); warp w owns rows i = w+8r.
    const bool q4ok = (l + 128) < C;
    float fm0 = fmsg_s[l];
    float fm1 = fmsg_s[l + 32];
    float fm2 = fmsg_s[l + 64];
    float fm3 = fmsg_s[l + 96];
    float fm4 = q4ok ? fmsg_s[l + 128] : 0.f;
    float c0 = 0.f, c1 = 0.f, c2 = 0.f, c3 = 0.f, c4 = 0.f;

    #pragma unroll 2
    for (int r = 0; r < 20; r++) {
        int i = w + 8*r;
        if (i >= C) break;
        const float* rp = aa_g + i*C;
        float v0 = rp[l];
        float v1 = rp[l + 32];
        float v2 = rp[l + 64];
        float v3 = rp[l + 96];
        float v4 = q4ok ? rp[l + 128] : 0.f;
        float mi = msg_s[i];                 // broadcast LDS
        c0 = fmaf(v0, mi, c0);
        c1 = fmaf(v1, mi, c1);
        c2 = fmaf(v2, mi, c2);
        c3 = fmaf(v3, mi, c3);
        c4 = fmaf(v4, mi, c4);
        float rs = v0*fm0 + v1*fm1 + v2*fm2 + v3*fm3 + v4*fm4;
        #pragma unroll
        for (int off = 16; off > 0; off >>= 1)
            rs += __shfl_xor_sync(0xFFFFFFFFu, rs, off);
        if (l == 0) row_s[i] = rs;
    }
    colpart[w][l]       = c0;
    colpart[w][l + 32]  = c1;
    colpart[w][l + 64]  = c2;
    colpart[w][l + 96]  = c3;
    if (q4ok) colpart[w][l + 128] = c4;
    __syncthreads();

    // ---- epilogue: qa + fused double-BCE partials ----
    float s = 0.f;
    if (t < C) {
        float col = 0.f;
        #pragma unroll
        for (int ww = 0; ww < 8; ww++) col += colpart[ww][t];
        float av = a[n*C + t];
        float tg = target[n*C + t];
        float x = av + col + row_s[t];
        float qa = 1.f / (1.f + expf(-x));
        out[n*C + t] = qa;
        float p1 = fminf(fmaxf(qa, EPSV), 1.f - EPSV);
        s  = tg*logf(p1) + (1.f - tg)*logf(1.f - p1);
        float p2 = 1.f / (1.f + expf(-av));
        p2 = fminf(fmaxf(p2, EPSV), 1.f - EPSV);
        s += tg*logf(p2) + (1.f - tg)*logf(1.f - p2);
    }
    sred[t] = s;
    __syncthreads();
    #pragma unroll
    for (int off = 128; off > 0; off >>= 1) {
        if (t < off) sred[t] += sred[t + off];
        __syncthreads();
    }
    if (t == 0) {
        g_partial[n] = sred[0];
        __threadfence();
        unsigned old = atomicAdd(&g_count, 1u);
        last_s = (old == N - 1);
    }
    __syncthreads();

    // ---- last CTA folds the 512 partials (deterministic fixed-order tree) ----
    if (last_s) {
        sred[t] = g_partial[t] + g_partial[t + 256];
        __syncthreads();
        #pragma unroll
        for (int off = 128; off > 0; off >>= 1) {
            if (t < off) sred[t] += sred[t + off];
            __syncthreads();
        }
        if (t == 0) {
            if (out_size > NC) out[NC] = -sred[0] / (3.0f * (float)NC);
            g_count = 0;        // reset for next graph replay
        }
    }
}

extern "C" void kernel_launch(void* const* d_in, const int* in_sizes, int n_in,
                              void* d_out, int out_size) {
    const float* a           = (const float*)d_in[0];
    const float* aa          = (const float*)d_in[1];
    const float* target      = (const float*)d_in[2];
    const float* bank_values = (const float*)d_in[3];
    const int*   bank_times  = (const int*)d_in[4];
    const int*   bank_mask   = (const int*)d_in[5];
    const int*   ids         = (const int*)d_in[6];
    const int*   times       = (const int*)d_in[7];
    float* out = (float*)d_out;

    fused_kernel<<<N, 256>>>(a, aa, target, bank_values, bank_times,
                             bank_mask, ids, times, out, out_size);
}

// round 5
// speedup vs baseline: 2.0760x; 1.2672x over previous
#include <cuda_runtime.h>
#include <math.h>

#define N 512
#define C 157
#define M 20
#define NC (N*C)
#define SIGMA2_INV (1.0f/(2.0f*300.0f*300.0f))
#define EPSV 1e-7f
#define INV_DECAY (1.0f/0.9f)
#define LOG2_INV_DECAY 0.15200309344504997f   /* log2(1/0.9) */
#define RPAD 33                                /* rowpart row pitch (conflict-free) */

__device__ float g_partial[N];
__device__ unsigned int g_count = 0;

__global__ __launch_bounds__(256) void fused_kernel(
    const float* __restrict__ a, const float* __restrict__ aa,
    const float* __restrict__ target, const float* __restrict__ bank_values,
    const int* __restrict__ bank_times, const int* __restrict__ bank_mask,
    const int* __restrict__ ids, const int* __restrict__ times,
    float* __restrict__ out, int out_size)
{
    __shared__ float msg_s[C], fmsg_s[C];
    __shared__ float rowpart[C * RPAD];     // [row][lane], pitch 33 -> conflict-free
    __shared__ float colpart[8][160];       // per-warp col partials
    __shared__ float wpast[M], wfut[M];
    __shared__ float denp_s, denf_s;
    __shared__ float wsum[8];
    __shared__ int last_s;

    const int n = blockIdx.x;
    const int t = threadIdx.x;
    const int w = t >> 5;
    const int l = t & 31;
    const int id = ids[n];
    const float* aa_g = aa + (size_t)n * (C*C);

    // ---- prefetch bank_values row + a/target into registers (before any barrier) ----
    float v[M];
    float av = 0.f, tg = 0.f;
    if (t < C) {
        const float* vals = bank_values + (size_t)id * (M*C);
        #pragma unroll
        for (int m = 0; m < M; m++) v[m] = vals[m*C + t];
        av = a[n*C + t];
        tg = target[n*C + t];
    }

    // ---- temporal weights: warp 0, ballot-rank ----
    if (t < 32) {
        const bool vd = l < M;
        int tsi = 0, mk = 0;
        if (vd) { tsi = bank_times[id*M + l]; mk = bank_mask[id*M + l]; }
        const float t0 = (float)times[n];
        float ts = (float)tsi;
        float d = ts - t0;
        float kern = expf(-d*d*SIGMA2_INV);
        bool condp = vd && mk && (ts < t0);
        bool condf = vd && mk && (ts > t0);
        unsigned bp = __ballot_sync(0xFFFFFFFFu, condp);
        unsigned bf = __ballot_sync(0xFFFFFFFFu, condf);
        unsigned below = (1u << l) - 1u;
        float dwp = condp ? exp2f(LOG2_INV_DECAY * (float)__popc(bp & below)) : 0.f;
        float dwf = condf ? exp2f(LOG2_INV_DECAY * (float)__popc(bf & below)) : 0.f;
        if (vd) { wpast[l] = dwp * kern; wfut[l] = dwf * kern; }
        if (l == 0) {
            float cp_ = (float)__popc(bp), cf_ = (float)__popc(bf);
            denp_s = (exp2f(LOG2_INV_DECAY * cp_) - 1.f) / (INV_DECAY - 1.f);
            denf_s = (exp2f(LOG2_INV_DECAY * cf_) - 1.f) / (INV_DECAY - 1.f);
        }
    }
    __syncthreads();

    // ---- msg/fmsg from registers (no LDG behind this barrier) ----
    if (t < C) {
        float nump = 0.f, numf = 0.f;
        #pragma unroll
        for (int m = 0; m < M; m++) {
            nump = fmaf(wpast[m], v[m], nump);
            numf = fmaf(wfut[m],  v[m], numf);
        }
        float denp = denp_s, denf = denf_s;
        msg_s[t]  = (denp > 0.f) ? nump / fmaxf(denp, EPSV) : 0.f;
        fmsg_s[t] = (denf > 0.f) ? numf / fmaxf(denf, EPSV) : 0.f;
    }
    __syncthreads();

    // ---- single streaming pass over aa; no cross-lane dependencies in loop ----
    // lane l owns cols j = l+32q (q<5); warp w owns rows i = w+8r (r<20).
    const bool q4ok = (l + 128) < C;
    float fm0 = fmsg_s[l];
    float fm1 = fmsg_s[l + 32];
    float fm2 = fmsg_s[l + 64];
    float fm3 = fmsg_s[l + 96];
    float fm4 = q4ok ? fmsg_s[l + 128] : 0.f;
    float c0 = 0.f, c1 = 0.f, c2 = 0.f, c3 = 0.f, c4 = 0.f;

    #pragma unroll 5
    for (int r = 0; r < 20; r++) {
        int i = w + 8*r;
        if (i < C) {
            const float* rp = aa_g + i*C;
            float v0 = rp[l];
            float v1 = rp[l + 32];
            float v2 = rp[l + 64];
            float v3 = rp[l + 96];
            float v4 = q4ok ? rp[l + 128] : 0.f;
            float mi = msg_s[i];                 // broadcast LDS
            c0 = fmaf(v0, mi, c0);
            c1 = fmaf(v1, mi, c1);
            c2 = fmaf(v2, mi, c2);
            c3 = fmaf(v3, mi, c3);
            c4 = fmaf(v4, mi, c4);
            // 3-deep tree, then scatter lane partial (no shuffle chain)
            float rs = fmaf(v0, fm0, v1*fm1) + fmaf(v2, fm2, v3*fm3) + v4*fm4;
            rowpart[i*RPAD + l] = rs;
        }
    }
    colpart[w][l]       = c0;
    colpart[w][l + 32]  = c1;
    colpart[w][l + 64]  = c2;
    colpart[w][l + 96]  = c3;
    if (q4ok) colpart[w][l + 128] = c4;
    __syncthreads();

    // ---- epilogue: fold partials, qa, fused double-BCE ----
    float s = 0.f;
    if (t < C) {
        float col = 0.f;
        #pragma unroll
        for (int ww = 0; ww < 8; ww++) col += colpart[ww][t];
        float r0 = 0.f, r1 = 0.f, r2 = 0.f, r3 = 0.f;
        const float* rp = rowpart + t*RPAD;
        #pragma unroll
        for (int j = 0; j < 32; j += 4) {
            r0 += rp[j]; r1 += rp[j+1]; r2 += rp[j+2]; r3 += rp[j+3];
        }
        float x = av + col + ((r0 + r1) + (r2 + r3));
        float qa = 1.f / (1.f + expf(-x));
        out[n*C + t] = qa;
        float p1 = fminf(fmaxf(qa, EPSV), 1.f - EPSV);
        s  = tg*logf(p1) + (1.f - tg)*logf(1.f - p1);
        float p2 = 1.f / (1.f + expf(-av));
        p2 = fminf(fmaxf(p2, EPSV), 1.f - EPSV);
        s += tg*logf(p2) + (1.f - tg)*logf(1.f - p2);
    }
    // one in-warp shuffle reduce + tiny cross-warp fold (single barrier)
    #pragma unroll
    for (int off = 16; off > 0; off >>= 1)
        s += __shfl_xor_sync(0xFFFFFFFFu, s, off);
    if (l == 0) wsum[w] = s;
    __syncthreads();
    if (t == 0) {
        float bs = ((wsum[0]+wsum[1]) + (wsum[2]+wsum[3]))
                 + ((wsum[4]+wsum[5]) + (wsum[6]+wsum[7]));
        g_partial[n] = bs;
        __threadfence();
        unsigned old = atomicAdd(&g_count, 1u);
        last_s = (old == N - 1);
    }
    __syncthreads();

    // ---- last CTA folds the 512 partials (deterministic fixed order) ----
    if (last_s) {
        float ps = g_partial[t] + g_partial[t + 256];
        #pragma unroll
        for (int off = 16; off > 0; off >>= 1)
            ps += __shfl_xor_sync(0xFFFFFFFFu, ps, off);
        if (l == 0) wsum[w] = ps;
        __syncthreads();
        if (t == 0) {
            float tot = ((wsum[0]+wsum[1]) + (wsum[2]+wsum[3]))
                      + ((wsum[4]+wsum[5]) + (wsum[6]+wsum[7]));
            if (out_size > NC) out[NC] = -tot / (3.0f * (float)NC);
            g_count = 0;        // reset for next graph replay
        }
    }
}

extern "C" void kernel_launch(void* const* d_in, const int* in_sizes, int n_in,
                              void* d_out, int out_size) {
    const float* a           = (const float*)d_in[0];
    const float* aa          = (const float*)d_in[1];
    const float* target      = (const float*)d_in[2];
    const float* bank_values = (const float*)d_in[3];
    const int*   bank_times  = (const int*)d_in[4];
    const int*   bank_mask   = (const int*)d_in[5];
    const int*   ids         = (const int*)d_in[6];
    const int*   times       = (const int*)d_in[7];
    float* out = (float*)d_out;

    fused_kernel<<<N, 256>>>(a, aa, target, bank_values, bank_times,
                             bank_mask, ids, times, out, out_size);
}

// round 6
// speedup vs baseline: 2.1228x; 1.0226x over previous
#include <cuda_runtime.h>
#include <math.h>

#define N 512
#define C 157
#define M 20
#define NC (N*C)
#define SIGMA2_INV (1.0f/(2.0f*300.0f*300.0f))
#define EPSV 1e-7f
#define INV_DECAY (1.0f/0.9f)
#define LOG2_INV_DECAY 0.15200309344504997f   /* log2(1/0.9) */
#define RPAD 33                                /* rowpart pitch (conflict-free) */
#define NW 12                                  /* warps per CTA */
#define NT (NW*32)                             /* 384 threads */

__device__ float g_partial[N];
__device__ unsigned int g_count = 0;

__global__ __launch_bounds__(NT, 4) void fused_kernel(
    const float* __restrict__ a, const float* __restrict__ aa,
    const float* __restrict__ target, const float* __restrict__ bank_values,
    const int* __restrict__ bank_times, const int* __restrict__ bank_mask,
    const int* __restrict__ ids, const int* __restrict__ times,
    float* __restrict__ out, int out_size)
{
    __shared__ float msg_s[C], fmsg_s[C];
    __shared__ float rowpart[C * RPAD];     // [row][lane]
    __shared__ float colpart[NW][160];      // per-warp col partials
    __shared__ float wpast[M], wfut[M];
    __shared__ float denp_s, denf_s;
    __shared__ float wsum[NW];
    __shared__ int last_s;

    const int n = blockIdx.x;
    const int t = threadIdx.x;
    const int w = t >> 5;
    const int l = t & 31;
    const int id = ids[n];
    const float* aa_g = aa + (size_t)n * (C*C);

    // ---- prefetch bank_values row + a/target into registers (before any barrier) ----
    float v[M];
    float av = 0.f, tg = 0.f;
    if (t < C) {
        const float* vals = bank_values + (size_t)id * (M*C);
        #pragma unroll
        for (int m = 0; m < M; m++) v[m] = vals[m*C + t];
        av = a[n*C + t];
        tg = target[n*C + t];
    }

    // ---- temporal weights: warp 0, ballot-rank ----
    if (t < 32) {
        const bool vd = l < M;
        int tsi = 0, mk = 0;
        if (vd) { tsi = bank_times[id*M + l]; mk = bank_mask[id*M + l]; }
        const float t0 = (float)times[n];
        float ts = (float)tsi;
        float d = ts - t0;
        float kern = expf(-d*d*SIGMA2_INV);
        bool condp = vd && mk && (ts < t0);
        bool condf = vd && mk && (ts > t0);
        unsigned bp = __ballot_sync(0xFFFFFFFFu, condp);
        unsigned bf = __ballot_sync(0xFFFFFFFFu, condf);
        unsigned below = (1u << l) - 1u;
        float dwp = condp ? exp2f(LOG2_INV_DECAY * (float)__popc(bp & below)) : 0.f;
        float dwf = condf ? exp2f(LOG2_INV_DECAY * (float)__popc(bf & below)) : 0.f;
        if (vd) { wpast[l] = dwp * kern; wfut[l] = dwf * kern; }
        if (l == 0) {
            float cp_ = (float)__popc(bp), cf_ = (float)__popc(bf);
            denp_s = (exp2f(LOG2_INV_DECAY * cp_) - 1.f) / (INV_DECAY - 1.f);
            denf_s = (exp2f(LOG2_INV_DECAY * cf_) - 1.f) / (INV_DECAY - 1.f);
        }
    }
    __syncthreads();

    // ---- msg/fmsg from registers (no LDG behind this barrier) ----
    if (t < C) {
        float nump = 0.f, numf = 0.f;
        #pragma unroll
        for (int m = 0; m < M; m++) {
            nump = fmaf(wpast[m], v[m], nump);
            numf = fmaf(wfut[m],  v[m], numf);
        }
        float denp = denp_s, denf = denf_s;
        msg_s[t]  = (denp > 0.f) ? nump / fmaxf(denp, EPSV) : 0.f;
        fmsg_s[t] = (denf > 0.f) ? numf / fmaxf(denf, EPSV) : 0.f;
    }
    __syncthreads();

    // ---- single streaming pass over aa; no cross-lane dependencies in loop ----
    // lane l owns cols j = l+32q (q<5); warp w owns rows i = w+NW*r.
    const bool q4ok = (l + 128) < C;
    float fm0 = fmsg_s[l];
    float fm1 = fmsg_s[l + 32];
    float fm2 = fmsg_s[l + 64];
    float fm3 = fmsg_s[l + 96];
    float fm4 = q4ok ? fmsg_s[l + 128] : 0.f;
    float c0 = 0.f, c1 = 0.f, c2 = 0.f, c3 = 0.f, c4 = 0.f;

    #pragma unroll 2
    for (int r = 0; r < 14; r++) {
        int i = w + NW*r;
        if (i < C) {
            const float* rp = aa_g + i*C;
            float v0 = rp[l];
            float v1 = rp[l + 32];
            float v2 = rp[l + 64];
            float v3 = rp[l + 96];
            float v4 = q4ok ? rp[l + 128] : 0.f;
            float mi = msg_s[i];                 // broadcast LDS
            c0 = fmaf(v0, mi, c0);
            c1 = fmaf(v1, mi, c1);
            c2 = fmaf(v2, mi, c2);
            c3 = fmaf(v3, mi, c3);
            c4 = fmaf(v4, mi, c4);
            float rs = fmaf(v0, fm0, v1*fm1) + fmaf(v2, fm2, v3*fm3) + v4*fm4;
            rowpart[i*RPAD + l] = rs;
        }
    }
    colpart[w][l]       = c0;
    colpart[w][l + 32]  = c1;
    colpart[w][l + 64]  = c2;
    colpart[w][l + 96]  = c3;
    if (q4ok) colpart[w][l + 128] = c4;
    __syncthreads();

    // ---- epilogue: fold partials, qa, fused double-BCE ----
    float s = 0.f;
    if (t < C) {
        float col = 0.f;
        #pragma unroll
        for (int ww = 0; ww < NW; ww++) col += colpart[ww][t];
        float r0 = 0.f, r1 = 0.f, r2 = 0.f, r3 = 0.f;
        const float* rp = rowpart + t*RPAD;
        #pragma unroll
        for (int j = 0; j < 32; j += 4) {
            r0 += rp[j]; r1 += rp[j+1]; r2 += rp[j+2]; r3 += rp[j+3];
        }
        float x = av + col + ((r0 + r1) + (r2 + r3));
        float qa = 1.f / (1.f + expf(-x));
        out[n*C + t] = qa;
        float p1 = fminf(fmaxf(qa, EPSV), 1.f - EPSV);
        s  = tg*logf(p1) + (1.f - tg)*logf(1.f - p1);
        float p2 = 1.f / (1.f + expf(-av));
        p2 = fminf(fmaxf(p2, EPSV), 1.f - EPSV);
        s += tg*logf(p2) + (1.f - tg)*logf(1.f - p2);
    }
    // one in-warp shuffle reduce + tiny cross-warp fold
    #pragma unroll
    for (int off = 16; off > 0; off >>= 1)
        s += __shfl_xor_sync(0xFFFFFFFFu, s, off);
    if (l == 0) wsum[w] = s;
    __syncthreads();
    if (t == 0) {
        float bs = 0.f;
        #pragma unroll
        for (int ww = 0; ww < NW; ww++) bs += wsum[ww];
        g_partial[n] = bs;
        __threadfence();
        unsigned old = atomicAdd(&g_count, 1u);
        last_s = (old == N - 1);
    }
    __syncthreads();

    // ---- last CTA folds the 512 partials (deterministic fixed order) ----
    if (last_s) {
        float ps = 0.f;
        if (t < 128)
            ps = (g_partial[t] + g_partial[t + 128])
               + (g_partial[t + 256] + g_partial[t + 384]);
        #pragma unroll
        for (int off = 16; off > 0; off >>= 1)
            ps += __shfl_xor_sync(0xFFFFFFFFu, ps, off);
        if (l == 0) wsum[w] = ps;
        __syncthreads();
        if (t == 0) {
            float tot = ((wsum[0] + wsum[1]) + (wsum[2] + wsum[3]));
            if (out_size > NC) out[NC] = -tot / (3.0f * (float)NC);
            g_count = 0;        // reset for next graph replay
        }
    }
}

extern "C" void kernel_launch(void* const* d_in, const int* in_sizes, int n_in,
                              void* d_out, int out_size) {
    const float* a           = (const float*)d_in[0];
    const float* aa          = (const float*)d_in[1];
    const float* target      = (const float*)d_in[2];
    const float* bank_values = (const float*)d_in[3];
    const int*   bank_times  = (const int*)d_in[4];
    const int*   bank_mask   = (const int*)d_in[5];
    const int*   ids         = (const int*)d_in[6];
    const int*   times       = (const int*)d_in[7];
    float* out = (float*)d_out;

    fused_kernel<<<N, NT>>>(a, aa, target, bank_values, bank_times,
                            bank_mask, ids, times, out, out_size);
}